// round 5
// baseline (speedup 1.0000x reference)
#include <cuda_runtime.h>

// IF spiking neuron forward, T=4. R5: persistent grid-stride kernel —
// exactly (SM count x occupancy) blocks, each thread strides over feature
// float4-chunks. Eliminates wave quantization / ragged tail (grid was 3072
// blocks = ~3 ragged waves in R4). Inner work identical to R4: batch loop
// in-thread (params read once per feature), plain LDG.128/STG.128.

#ifndef T_STEPS
#define T_STEPS 4
#endif

__global__ __launch_bounds__(256) void if_fwd_kernel(
    const float4* __restrict__ x,      // [T, B, N4]
    const float4* __restrict__ thre,   // [N4]
    const float4* __restrict__ dtm,    // [N4]
    float4* __restrict__ out,          // [T, B, N4]
    long long N4,
    int B)
{
    const long long stride = (long long)gridDim.x * blockDim.x;
    const long long tstride = (long long)B * N4;

    for (long long f = (long long)blockIdx.x * blockDim.x + threadIdx.x;
         f < N4; f += stride) {

        const float4 th = thre[f];
        float4 m0 = dtm[f];
        m0.x *= th.x; m0.y *= th.y; m0.z *= th.z; m0.w *= th.w;

        const float4* xp = x + f;
        float4* op = out + f;

#pragma unroll 1
        for (int b = 0; b < B; b++) {
            float4 xv0 = xp[0 * tstride];
            float4 xv1 = xp[1 * tstride];
            float4 xv2 = xp[2 * tstride];
            float4 xv3 = xp[3 * tstride];

            float4 mem = m0;
            float4 s;

            // t = 0
            mem.x += xv0.x; mem.y += xv0.y; mem.z += xv0.z; mem.w += xv0.w;
            s.x = (mem.x >= th.x) ? th.x : 0.0f;
            s.y = (mem.y >= th.y) ? th.y : 0.0f;
            s.z = (mem.z >= th.z) ? th.z : 0.0f;
            s.w = (mem.w >= th.w) ? th.w : 0.0f;
            op[0 * tstride] = s;
            mem.x -= s.x; mem.y -= s.y; mem.z -= s.z; mem.w -= s.w;

            // t = 1
            mem.x += xv1.x; mem.y += xv1.y; mem.z += xv1.z; mem.w += xv1.w;
            s.x = (mem.x >= th.x) ? th.x : 0.0f;
            s.y = (mem.y >= th.y) ? th.y : 0.0f;
            s.z = (mem.z >= th.z) ? th.z : 0.0f;
            s.w = (mem.w >= th.w) ? th.w : 0.0f;
            op[1 * tstride] = s;
            mem.x -= s.x; mem.y -= s.y; mem.z -= s.z; mem.w -= s.w;

            // t = 2
            mem.x += xv2.x; mem.y += xv2.y; mem.z += xv2.z; mem.w += xv2.w;
            s.x = (mem.x >= th.x) ? th.x : 0.0f;
            s.y = (mem.y >= th.y) ? th.y : 0.0f;
            s.z = (mem.z >= th.z) ? th.z : 0.0f;
            s.w = (mem.w >= th.w) ? th.w : 0.0f;
            op[2 * tstride] = s;
            mem.x -= s.x; mem.y -= s.y; mem.z -= s.z; mem.w -= s.w;

            // t = 3
            mem.x += xv3.x; mem.y += xv3.y; mem.z += xv3.z; mem.w += xv3.w;
            s.x = (mem.x >= th.x) ? th.x : 0.0f;
            s.y = (mem.y >= th.y) ? th.y : 0.0f;
            s.z = (mem.z >= th.z) ? th.z : 0.0f;
            s.w = (mem.w >= th.w) ? th.w : 0.0f;
            op[3 * tstride] = s;

            xp += N4;
            op += N4;
        }
    }
}

extern "C" void kernel_launch(void* const* d_in, const int* in_sizes, int n_in,
                              void* d_out, int out_size)
{
    const float* x   = (const float*)d_in[0];
    const float* th  = (const float*)d_in[1];
    const float* dtm = (const float*)d_in[2];
    float* out = (float*)d_out;

    const long long N = in_sizes[1];                   // 1024*3072
    const int B = (int)(in_sizes[0] / (T_STEPS * N));  // 8
    const long long N4 = N / 4;

    const int threads = 256;

    int dev = 0;
    cudaGetDevice(&dev);
    int sm_count = 148;
    cudaDeviceGetAttribute(&sm_count, cudaDevAttrMultiProcessorCount, dev);

    int blocks_per_sm = 6;
    cudaOccupancyMaxActiveBlocksPerMultiprocessor(
        &blocks_per_sm, if_fwd_kernel, threads, 0);
    if (blocks_per_sm < 1) blocks_per_sm = 1;

    long long grid = (long long)sm_count * blocks_per_sm;
    long long max_grid = (N4 + threads - 1) / threads;
    if (grid > max_grid) grid = max_grid;

    if_fwd_kernel<<<(unsigned)grid, threads>>>(
        (const float4*)x, (const float4*)th, (const float4*)dtm,
        (float4*)out, N4, B);
}

// round 6
// speedup vs baseline: 1.1198x; 1.1198x over previous
#include <cuda_runtime.h>

// IF spiking neuron forward, T=4. R6: R1's high-parallelism layout
// (thread per (feature-float4, batch), 24576 blocks, 32 regs, ~84% occ,
// best measured BW 6849 GB/s) with the grid axes SWAPPED so batch varies
// fastest: consecutive blocks cover all 8 batches of the same feature
// window and share the thresh2/dtmem lines in L2 (param DRAM traffic
// ~150 MB -> ~25 MB). Minimal traffic + maximal concurrency.

#ifndef T_STEPS
#define T_STEPS 4
#endif

__global__ __launch_bounds__(256) void if_fwd_kernel(
    const float4* __restrict__ x,      // [T, B, N4]
    const float4* __restrict__ thre,   // [N4]
    const float4* __restrict__ dtm,    // [N4]
    float4* __restrict__ out,          // [T, B, N4]
    long long N4,
    int B)
{
    long long f = (long long)blockIdx.y * blockDim.x + threadIdx.x;
    if (f >= N4) return;
    const int b = blockIdx.x;   // batch fastest-varying -> L2 param sharing

    const float4 th = thre[f];
    float4 mem = dtm[f];
    mem.x *= th.x; mem.y *= th.y; mem.z *= th.z; mem.w *= th.w;

    const long long tstride = (long long)B * N4;
    const float4* xp = x + (long long)b * N4 + f;
    float4* op = out + (long long)b * N4 + f;

    // Front-batch the 4 independent loads (MLP=4).
    float4 xv0 = xp[0 * tstride];
    float4 xv1 = xp[1 * tstride];
    float4 xv2 = xp[2 * tstride];
    float4 xv3 = xp[3 * tstride];

    float4 s;

    // t = 0
    mem.x += xv0.x; mem.y += xv0.y; mem.z += xv0.z; mem.w += xv0.w;
    s.x = (mem.x >= th.x) ? th.x : 0.0f;
    s.y = (mem.y >= th.y) ? th.y : 0.0f;
    s.z = (mem.z >= th.z) ? th.z : 0.0f;
    s.w = (mem.w >= th.w) ? th.w : 0.0f;
    op[0 * tstride] = s;
    mem.x -= s.x; mem.y -= s.y; mem.z -= s.z; mem.w -= s.w;

    // t = 1
    mem.x += xv1.x; mem.y += xv1.y; mem.z += xv1.z; mem.w += xv1.w;
    s.x = (mem.x >= th.x) ? th.x : 0.0f;
    s.y = (mem.y >= th.y) ? th.y : 0.0f;
    s.z = (mem.z >= th.z) ? th.z : 0.0f;
    s.w = (mem.w >= th.w) ? th.w : 0.0f;
    op[1 * tstride] = s;
    mem.x -= s.x; mem.y -= s.y; mem.z -= s.z; mem.w -= s.w;

    // t = 2
    mem.x += xv2.x; mem.y += xv2.y; mem.z += xv2.z; mem.w += xv2.w;
    s.x = (mem.x >= th.x) ? th.x : 0.0f;
    s.y = (mem.y >= th.y) ? th.y : 0.0f;
    s.z = (mem.z >= th.z) ? th.z : 0.0f;
    s.w = (mem.w >= th.w) ? th.w : 0.0f;
    op[2 * tstride] = s;
    mem.x -= s.x; mem.y -= s.y; mem.z -= s.z; mem.w -= s.w;

    // t = 3 (no trailing mem update needed)
    mem.x += xv3.x; mem.y += xv3.y; mem.z += xv3.z; mem.w += xv3.w;
    s.x = (mem.x >= th.x) ? th.x : 0.0f;
    s.y = (mem.y >= th.y) ? th.y : 0.0f;
    s.z = (mem.z >= th.z) ? th.z : 0.0f;
    s.w = (mem.w >= th.w) ? th.w : 0.0f;
    op[3 * tstride] = s;
}

extern "C" void kernel_launch(void* const* d_in, const int* in_sizes, int n_in,
                              void* d_out, int out_size)
{
    const float* x   = (const float*)d_in[0];
    const float* th  = (const float*)d_in[1];
    const float* dtm = (const float*)d_in[2];
    float* out = (float*)d_out;

    const long long N = in_sizes[1];                   // 1024*3072
    const int B = (int)(in_sizes[0] / (T_STEPS * N));  // 8
    const long long N4 = N / 4;

    const int threads = 256;
    dim3 grid((unsigned)B, (unsigned)((N4 + threads - 1) / threads));

    if_fwd_kernel<<<grid, threads>>>(
        (const float4*)x, (const float4*)th, (const float4*)dtm,
        (float4*)out, N4, B);
}